// round 1
// baseline (speedup 1.0000x reference)
#include <cuda_runtime.h>
#include <cuda_bf16.h>
#include <cstddef>

// ---------------------------------------------------------------------------
// EarthAttention3D (Pangu-Weather) — Round 0 baseline, fp32 throughout.
// Shapes (fixed): B_=960 windows, L=144, C=192, H=6, hd=32, nw=64, w_wins=15.
// Pipeline: [QKV GEMM] -> [fused attention per (window, head)] -> [out-proj GEMM]
// ---------------------------------------------------------------------------

#define B_WIN   960
#define SEQ_L   144
#define DIM_C   192
#define NHEADS  6
#define HEADD   32
#define NWGRP   64
#define WWINS   15
#define QKVC    576           // 3*C
#define QPAD    33            // padded smem row stride for q/k/v (kills 16-way conflicts)

// Scratch (allowed: __device__ globals)
__device__ float g_qkv[(size_t)B_WIN * SEQ_L * QKVC];   // ~318 MB
__device__ float g_ctx[(size_t)B_WIN * SEQ_L * DIM_C];  // ~106 MB

// ---------------------------------------------------------------------------
// Generic tiled fp32 GEMM:  C[M,N] = A[M,K] @ B[K,N] + bias[N]
// BM=BN=64, BK=32, 256 threads, 4x4 micro-tile. M%64==0, N%64==0, K%32==0.
// ---------------------------------------------------------------------------
__global__ __launch_bounds__(256) void gemm_bias_kernel(
    const float* __restrict__ A, const float* __restrict__ B,
    const float* __restrict__ bias, float* __restrict__ C,
    int M, int N, int K)
{
    __shared__ float As[32][64 + 4];   // transposed: As[k][m]
    __shared__ float Bs[32][64];

    const int bm  = blockIdx.y * 64;
    const int bn  = blockIdx.x * 64;
    const int tid = threadIdx.x;
    const int tx  = tid & 15;
    const int ty  = tid >> 4;

    float acc[4][4] = {};

    for (int k0 = 0; k0 < K; k0 += 32) {
        // Load A tile (64 rows x 32 cols), coalesced 128B per warp-row
        #pragma unroll
        for (int i = 0; i < 8; i++) {
            int idx = tid + i * 256;
            int m = idx >> 5, k = idx & 31;
            As[k][m] = A[(size_t)(bm + m) * K + (k0 + k)];
        }
        // Load B tile (32 rows x 64 cols)
        #pragma unroll
        for (int i = 0; i < 8; i++) {
            int idx = tid + i * 256;
            int k = idx >> 6, n = idx & 63;
            Bs[k][n] = B[(size_t)(k0 + k) * N + (bn + n)];
        }
        __syncthreads();

        #pragma unroll
        for (int k = 0; k < 32; k++) {
            float a[4], b[4];
            #pragma unroll
            for (int i = 0; i < 4; i++) a[i] = As[k][ty * 4 + i];
            #pragma unroll
            for (int j = 0; j < 4; j++) b[j] = Bs[k][tx * 4 + j];
            #pragma unroll
            for (int i = 0; i < 4; i++)
                #pragma unroll
                for (int j = 0; j < 4; j++)
                    acc[i][j] += a[i] * b[j];
        }
        __syncthreads();
    }

    #pragma unroll
    for (int i = 0; i < 4; i++) {
        int row = bm + ty * 4 + i;
        #pragma unroll
        for (int j = 0; j < 4; j++) {
            int col = bn + tx * 4 + j;
            C[(size_t)row * N + col] = acc[i][j] + bias[col];
        }
    }
}

// ---------------------------------------------------------------------------
// Fused attention: one block per (head, window). 256 threads.
// smem: q/k/v (144 x 33 each) + scores (144 x 144)  = 139,968 bytes dynamic.
// ---------------------------------------------------------------------------
__global__ __launch_bounds__(256) void attn_kernel(
    const float* __restrict__ qkv,
    const float* __restrict__ mask,
    const float* __restrict__ bias_table,
    const int*   __restrict__ pos,
    float*       __restrict__ ctx)
{
    const int head = blockIdx.x;            // 0..5
    const int bwin = blockIdx.y;            // 0..959
    const int nw   = (bwin / WWINS) % NWGRP;

    extern __shared__ float sm[];
    float* qS = sm;                          // 144*33
    float* kS = qS + SEQ_L * QPAD;
    float* vS = kS + SEQ_L * QPAD;
    float* sS = vS + SEQ_L * QPAD;           // 144*144

    const int tid = threadIdx.x;
    const float scale = 0.17677669529663687f;  // 32^-0.5

    // --- load q,k,v for this (window, head) ---
    const size_t base = (size_t)bwin * SEQ_L * QKVC;
    for (int idx = tid; idx < SEQ_L * HEADD; idx += 256) {
        int l = idx >> 5, d = idx & 31;
        size_t rb = base + (size_t)l * QKVC + head * HEADD;
        qS[l * QPAD + d] = qkv[rb + 0 * DIM_C + d] * scale;
        kS[l * QPAD + d] = qkv[rb + 1 * DIM_C + d];
        vS[l * QPAD + d] = qkv[rb + 2 * DIM_C + d];
    }
    __syncthreads();

    const int tx = tid & 15;    // 16 col-groups
    const int ty = tid >> 4;    // 16 row-groups

    // --- scores: S = q @ k^T  (9x9 register micro-tile per thread) ---
    {
        float acc[9][9] = {};
        #pragma unroll 4
        for (int d = 0; d < HEADD; d++) {
            float a[9], b[9];
            #pragma unroll
            for (int i = 0; i < 9; i++) a[i] = qS[(ty * 9 + i) * QPAD + d];
            #pragma unroll
            for (int j = 0; j < 9; j++) b[j] = kS[(tx * 9 + j) * QPAD + d];
            #pragma unroll
            for (int i = 0; i < 9; i++)
                #pragma unroll
                for (int j = 0; j < 9; j++)
                    acc[i][j] += a[i] * b[j];
        }
        #pragma unroll
        for (int i = 0; i < 9; i++)
            #pragma unroll
            for (int j = 0; j < 9; j++)
                sS[(ty * 9 + i) * SEQ_L + tx * 9 + j] = acc[i][j];
    }
    __syncthreads();

    // --- bias gather (L2-resident table) + mask add ---
    {
        const float* mrow = mask + (size_t)bwin * SEQ_L * SEQ_L;
        for (int idx = tid; idx < SEQ_L * SEQ_L; idx += 256) {
            int p = pos[idx];
            sS[idx] += bias_table[(size_t)p * (NWGRP * NHEADS) + nw * NHEADS + head]
                     + mrow[idx];
        }
    }
    __syncthreads();

    // --- softmax per row (warp per row) ---
    {
        const int warp = tid >> 5, lane = tid & 31;
        for (int r = warp; r < SEQ_L; r += 8) {
            float* row = sS + r * SEQ_L;
            float mx = -1e30f;
            for (int m = lane; m < SEQ_L; m += 32) mx = fmaxf(mx, row[m]);
            #pragma unroll
            for (int o = 16; o > 0; o >>= 1)
                mx = fmaxf(mx, __shfl_xor_sync(0xffffffffu, mx, o));
            float sum = 0.f;
            for (int m = lane; m < SEQ_L; m += 32) {
                float e = __expf(row[m] - mx);
                row[m] = e;
                sum += e;
            }
            #pragma unroll
            for (int o = 16; o > 0; o >>= 1)
                sum += __shfl_xor_sync(0xffffffffu, sum, o);
            float inv = 1.f / sum;
            for (int m = lane; m < SEQ_L; m += 32) row[m] *= inv;
        }
    }
    __syncthreads();

    // --- ctx = P @ V  (9 rows x 2 cols per thread) ---
    {
        float acc[9][2] = {};
        for (int m = 0; m < SEQ_L; m++) {
            float b0 = vS[m * QPAD + tx * 2];
            float b1 = vS[m * QPAD + tx * 2 + 1];
            #pragma unroll
            for (int i = 0; i < 9; i++) {
                float p = sS[(ty * 9 + i) * SEQ_L + m];
                acc[i][0] += p * b0;
                acc[i][1] += p * b1;
            }
        }
        const size_t obase = (size_t)bwin * SEQ_L * DIM_C + head * HEADD;
        #pragma unroll
        for (int i = 0; i < 9; i++) {
            int l = ty * 9 + i;
            ctx[obase + (size_t)l * DIM_C + tx * 2]     = acc[i][0];
            ctx[obase + (size_t)l * DIM_C + tx * 2 + 1] = acc[i][1];
        }
    }
}

// ---------------------------------------------------------------------------
extern "C" void kernel_launch(void* const* d_in, const int* in_sizes, int n_in,
                              void* d_out, int out_size)
{
    (void)in_sizes; (void)n_in; (void)out_size;
    const float* x          = (const float*)d_in[0];
    const float* mask       = (const float*)d_in[1];
    const float* W1         = (const float*)d_in[2];
    const float* b1         = (const float*)d_in[3];
    const float* W2         = (const float*)d_in[4];
    const float* b2         = (const float*)d_in[5];
    const float* bias_table = (const float*)d_in[6];
    const int*   pos        = (const int*)d_in[7];
    float*       out        = (float*)d_out;

    float* qkv;  cudaGetSymbolAddress((void**)&qkv, g_qkv);
    float* ctx;  cudaGetSymbolAddress((void**)&ctx, g_ctx);

    const int M = B_WIN * SEQ_L;  // 138240

    // 1) QKV projection: (138240 x 192) @ (192 x 576) + b1
    gemm_bias_kernel<<<dim3(QKVC / 64, M / 64), 256>>>(x, W1, b1, qkv, M, QKVC, DIM_C);

    // 2) Fused attention
    const int smem_bytes = (3 * SEQ_L * QPAD + SEQ_L * SEQ_L) * (int)sizeof(float); // 139968
    cudaFuncSetAttribute(attn_kernel, cudaFuncAttributeMaxDynamicSharedMemorySize, smem_bytes);
    attn_kernel<<<dim3(NHEADS, B_WIN), 256, smem_bytes>>>(qkv, mask, bias_table, pos, ctx);

    // 3) Output projection: (138240 x 192) @ (192 x 192) + b2
    gemm_bias_kernel<<<dim3(DIM_C / 64, M / 64), 256>>>(ctx, W2, b2, out, M, DIM_C, DIM_C);
}

// round 2
// speedup vs baseline: 1.7240x; 1.7240x over previous
#include <cuda_runtime.h>
#include <cuda_bf16.h>
#include <cstdint>
#include <cstddef>

// ---------------------------------------------------------------------------
// EarthAttention3D — Round 1: tf32 mma.sync everywhere.
// Shapes: B_=960, L=144, C=192, H=6, hd=32, nw=64, w_wins=15.
// ---------------------------------------------------------------------------

#define B_WIN   960
#define SEQ_L   144
#define DIM_C   192
#define NHEADS  6
#define HEADD   32
#define NWGRP   64
#define WWINS   15
#define QKVC    576

#define QP      36     // q/k smem row stride (bank-conflict-free frags: 4g+tg)
#define VP      40     // v smem row stride (8tg+g)
#define SP      148    // scores smem row stride (20g+tg)

__device__ float g_qkv[(size_t)B_WIN * SEQ_L * QKVC];
__device__ float g_ctx[(size_t)B_WIN * SEQ_L * DIM_C];

__device__ __forceinline__ float tf32r(float x) {
    uint32_t u;
    asm("cvt.rna.tf32.f32 %0, %1;" : "=r"(u) : "f"(x));
    return __uint_as_float(u);
}

__device__ __forceinline__ void mma_tf32(float c[4], const uint32_t a[4], const uint32_t b[2]) {
    asm volatile(
        "mma.sync.aligned.m16n8k8.row.col.f32.tf32.tf32.f32 "
        "{%0,%1,%2,%3}, {%4,%5,%6,%7}, {%8,%9}, {%0,%1,%2,%3};"
        : "+f"(c[0]), "+f"(c[1]), "+f"(c[2]), "+f"(c[3])
        : "r"(a[0]), "r"(a[1]), "r"(a[2]), "r"(a[3]), "r"(b[0]), "r"(b[1]));
}

// ---------------------------------------------------------------------------
// tf32 GEMM:  C[M,N] = A[M,K] @ B[K,N] + bias[N]
// BM=128, BN=64, BK=32, 256 threads, 8 warps as 4(M)x2(N), warp tile 32x32.
// Requires M%128==0, N%64==0, K%32==0.
// ---------------------------------------------------------------------------
__global__ __launch_bounds__(256) void gemm_tf32_kernel(
    const float* __restrict__ A, const float* __restrict__ B,
    const float* __restrict__ bias, float* __restrict__ C,
    int M, int N, int K)
{
    __shared__ float As[128][QP];   // [m][k], stride 36
    __shared__ float Bs[32][72];    // [k][n], stride 72

    const int bm   = blockIdx.y * 128;
    const int bn   = blockIdx.x * 64;
    const int tid  = threadIdx.x;
    const int w    = tid >> 5;
    const int lane = tid & 31;
    const int g    = lane >> 2;
    const int tg   = lane & 3;
    const int wm   = (w >> 1) * 32;
    const int wn   = (w & 1) * 32;

    float acc[2][4][4] = {};

    for (int k0 = 0; k0 < K; k0 += 32) {
        // A tile: 128x32 = 1024 float4, 4 per thread
        #pragma unroll
        for (int i = 0; i < 4; i++) {
            int idx = tid + i * 256;
            int r = idx >> 3, c = (idx & 7) * 4;
            float4 v = *(const float4*)&A[(size_t)(bm + r) * K + k0 + c];
            As[r][c + 0] = tf32r(v.x); As[r][c + 1] = tf32r(v.y);
            As[r][c + 2] = tf32r(v.z); As[r][c + 3] = tf32r(v.w);
        }
        // B tile: 32x64 = 512 float4, 2 per thread
        #pragma unroll
        for (int i = 0; i < 2; i++) {
            int idx = tid + i * 256;
            int r = idx >> 4, c = (idx & 15) * 4;
            float4 v = *(const float4*)&B[(size_t)(k0 + r) * N + bn + c];
            Bs[r][c + 0] = tf32r(v.x); Bs[r][c + 1] = tf32r(v.y);
            Bs[r][c + 2] = tf32r(v.z); Bs[r][c + 3] = tf32r(v.w);
        }
        __syncthreads();

        #pragma unroll
        for (int kk = 0; kk < 4; kk++) {
            const int k = kk * 8;
            uint32_t af[2][4], bf[4][2];
            #pragma unroll
            for (int mt = 0; mt < 2; mt++) {
                int r0 = wm + mt * 16 + g;
                af[mt][0] = __float_as_uint(As[r0][k + tg]);
                af[mt][1] = __float_as_uint(As[r0 + 8][k + tg]);
                af[mt][2] = __float_as_uint(As[r0][k + tg + 4]);
                af[mt][3] = __float_as_uint(As[r0 + 8][k + tg + 4]);
            }
            #pragma unroll
            for (int nt = 0; nt < 4; nt++) {
                int cn = wn + nt * 8 + g;
                bf[nt][0] = __float_as_uint(Bs[k + tg][cn]);
                bf[nt][1] = __float_as_uint(Bs[k + tg + 4][cn]);
            }
            #pragma unroll
            for (int mt = 0; mt < 2; mt++)
                #pragma unroll
                for (int nt = 0; nt < 4; nt++)
                    mma_tf32(acc[mt][nt], af[mt], bf[nt]);
        }
        __syncthreads();
    }

    #pragma unroll
    for (int mt = 0; mt < 2; mt++) {
        #pragma unroll
        for (int nt = 0; nt < 4; nt++) {
            int r0  = bm + wm + mt * 16 + g;
            int col = bn + wn + nt * 8 + 2 * tg;
            float b0 = bias[col], b1 = bias[col + 1];
            C[(size_t)r0 * N + col]           = acc[mt][nt][0] + b0;
            C[(size_t)r0 * N + col + 1]       = acc[mt][nt][1] + b1;
            C[(size_t)(r0 + 8) * N + col]     = acc[mt][nt][2] + b0;
            C[(size_t)(r0 + 8) * N + col + 1] = acc[mt][nt][3] + b1;
        }
    }
}

// ---------------------------------------------------------------------------
// Fused attention, tf32 mma. One block per (head, window). 288 threads, 9 warps.
// Warp w owns rows [16w, 16w+16): computes S band, fused bias+mask epilogue,
// warp-private softmax, then P@V — only __syncwarp between phases.
// ---------------------------------------------------------------------------
__global__ __launch_bounds__(288) void attn_tf32_kernel(
    const float* __restrict__ qkv,
    const float* __restrict__ mask,
    const float* __restrict__ bias_table,
    const int*   __restrict__ pos,
    float*       __restrict__ ctx)
{
    const int head = blockIdx.x;
    const int bwin = blockIdx.y;
    const int nw   = (bwin / WWINS) % NWGRP;

    extern __shared__ float sm[];
    float* qS = sm;                       // 144*36
    float* kS = qS + SEQ_L * QP;          // 144*36
    float* vS = kS + SEQ_L * QP;          // 144*40
    float* sS = vS + SEQ_L * VP;          // 144*148

    const int tid = threadIdx.x;
    const float scale = 0.17677669529663687f;

    // --- load q,k,v (cvt to tf32; q pre-scaled) ---
    {
        const size_t base = (size_t)bwin * SEQ_L * QKVC + head * HEADD;
        for (int idx = tid; idx < SEQ_L * HEADD; idx += 288) {
            int l = idx >> 5, d = idx & 31;
            size_t rb = base + (size_t)l * QKVC;
            qS[l * QP + d] = tf32r(qkv[rb + d] * scale);
            kS[l * QP + d] = tf32r(qkv[rb + DIM_C + d]);
            vS[l * VP + d] = tf32r(qkv[rb + 2 * DIM_C + d]);
        }
    }
    __syncthreads();

    const int w    = tid >> 5;
    const int lane = tid & 31;
    const int g    = lane >> 2;
    const int tg   = lane & 3;
    const int r0   = 16 * w + g;          // this lane's base row

    // --- S = q @ k^T for own band: accS[18 n-tiles][4] ---
    float accS[18][4] = {};
    #pragma unroll
    for (int kk = 0; kk < 4; kk++) {
        const int k = kk * 8;
        uint32_t af[4];
        af[0] = __float_as_uint(qS[r0 * QP + k + tg]);
        af[1] = __float_as_uint(qS[(r0 + 8) * QP + k + tg]);
        af[2] = __float_as_uint(qS[r0 * QP + k + tg + 4]);
        af[3] = __float_as_uint(qS[(r0 + 8) * QP + k + tg + 4]);
        #pragma unroll
        for (int nt = 0; nt < 18; nt++) {
            int cn = nt * 8 + g;
            uint32_t bf[2];
            bf[0] = __float_as_uint(kS[cn * QP + k + tg]);
            bf[1] = __float_as_uint(kS[cn * QP + k + tg + 4]);
            mma_tf32(accS[nt], af, bf);
        }
    }

    // --- epilogue: + earth bias (gather) + mask, store to sS ---
    {
        const float* mrow = mask + (size_t)bwin * SEQ_L * SEQ_L;
        const int boff = nw * NHEADS + head;
        #pragma unroll
        for (int nt = 0; nt < 18; nt++) {
            int col = nt * 8 + 2 * tg;
            int i00 = r0 * SEQ_L + col;
            int i10 = (r0 + 8) * SEQ_L + col;
            sS[r0 * SP + col]           = accS[nt][0] + mrow[i00]     + bias_table[(size_t)pos[i00]     * (NWGRP * NHEADS) + boff];
            sS[r0 * SP + col + 1]       = accS[nt][1] + mrow[i00 + 1] + bias_table[(size_t)pos[i00 + 1] * (NWGRP * NHEADS) + boff];
            sS[(r0 + 8) * SP + col]     = accS[nt][2] + mrow[i10]     + bias_table[(size_t)pos[i10]     * (NWGRP * NHEADS) + boff];
            sS[(r0 + 8) * SP + col + 1] = accS[nt][3] + mrow[i10 + 1] + bias_table[(size_t)pos[i10 + 1] * (NWGRP * NHEADS) + boff];
        }
    }
    __syncwarp();

    // --- softmax over own 16 rows (warp-parallel across columns) ---
    for (int r = 16 * w; r < 16 * w + 16; r++) {
        float* row = sS + r * SP;
        float mx = -1e30f;
        for (int m = lane; m < SEQ_L; m += 32) mx = fmaxf(mx, row[m]);
        #pragma unroll
        for (int o = 16; o > 0; o >>= 1)
            mx = fmaxf(mx, __shfl_xor_sync(0xffffffffu, mx, o));
        float sum = 0.f;
        for (int m = lane; m < SEQ_L; m += 32) {
            float e = __expf(row[m] - mx);
            row[m] = e;
            sum += e;
        }
        #pragma unroll
        for (int o = 16; o > 0; o >>= 1)
            sum += __shfl_xor_sync(0xffffffffu, sum, o);
        float inv = 1.f / sum;
        for (int m = lane; m < SEQ_L; m += 32) row[m] = tf32r(row[m] * inv);
    }
    __syncwarp();

    // --- ctx = P @ V for own band: acco[4 n-tiles][4] ---
    float acco[4][4] = {};
    #pragma unroll
    for (int kt = 0; kt < 18; kt++) {
        const int k = kt * 8;
        uint32_t af[4];
        af[0] = __float_as_uint(sS[r0 * SP + k + tg]);
        af[1] = __float_as_uint(sS[(r0 + 8) * SP + k + tg]);
        af[2] = __float_as_uint(sS[r0 * SP + k + tg + 4]);
        af[3] = __float_as_uint(sS[(r0 + 8) * SP + k + tg + 4]);
        #pragma unroll
        for (int nt = 0; nt < 4; nt++) {
            uint32_t bf[2];
            bf[0] = __float_as_uint(vS[(k + tg) * VP + nt * 8 + g]);
            bf[1] = __float_as_uint(vS[(k + tg + 4) * VP + nt * 8 + g]);
            mma_tf32(acco[nt], af, bf);
        }
    }

    {
        const size_t obase = (size_t)bwin * SEQ_L * DIM_C + head * HEADD;
        #pragma unroll
        for (int nt = 0; nt < 4; nt++) {
            int col = nt * 8 + 2 * tg;
            ctx[obase + (size_t)r0 * DIM_C + col]           = acco[nt][0];
            ctx[obase + (size_t)r0 * DIM_C + col + 1]       = acco[nt][1];
            ctx[obase + (size_t)(r0 + 8) * DIM_C + col]     = acco[nt][2];
            ctx[obase + (size_t)(r0 + 8) * DIM_C + col + 1] = acco[nt][3];
        }
    }
}

// ---------------------------------------------------------------------------
extern "C" void kernel_launch(void* const* d_in, const int* in_sizes, int n_in,
                              void* d_out, int out_size)
{
    (void)in_sizes; (void)n_in; (void)out_size;
    const float* x          = (const float*)d_in[0];
    const float* mask       = (const float*)d_in[1];
    const float* W1         = (const float*)d_in[2];
    const float* b1         = (const float*)d_in[3];
    const float* W2         = (const float*)d_in[4];
    const float* b2         = (const float*)d_in[5];
    const float* bias_table = (const float*)d_in[6];
    const int*   pos        = (const int*)d_in[7];
    float*       out        = (float*)d_out;

    float* qkv;  cudaGetSymbolAddress((void**)&qkv, g_qkv);
    float* ctx;  cudaGetSymbolAddress((void**)&ctx, g_ctx);

    const int M = B_WIN * SEQ_L;  // 138240

    // 1) QKV projection (tf32 MMA)
    gemm_tf32_kernel<<<dim3(QKVC / 64, M / 128), 256>>>(x, W1, b1, qkv, M, QKVC, DIM_C);

    // 2) Fused attention (tf32 MMA)
    const int smem_bytes = (2 * SEQ_L * QP + SEQ_L * VP + SEQ_L * SP) * (int)sizeof(float); // 149760
    cudaFuncSetAttribute(attn_tf32_kernel, cudaFuncAttributeMaxDynamicSharedMemorySize, smem_bytes);
    attn_tf32_kernel<<<dim3(NHEADS, B_WIN), 288, smem_bytes>>>(qkv, mask, bias_table, pos, ctx);

    // 3) Output projection (tf32 MMA)
    gemm_tf32_kernel<<<dim3(DIM_C / 64, M / 128), 256>>>(ctx, W2, b2, out, M, DIM_C, DIM_C);
}

// round 3
// speedup vs baseline: 3.8006x; 2.2045x over previous
#include <cuda_runtime.h>
#include <cuda_bf16.h>
#include <cstdint>
#include <cstddef>

// ---------------------------------------------------------------------------
// EarthAttention3D — Round 3: register-resident attention + materialized bias
//                    + cp.async double-buffered tf32 GEMMs.
// Shapes: B_=960, L=144, C=192, H=6, hd=32, nw=64, w_wins=15.
// ---------------------------------------------------------------------------

#define B_WIN   960
#define SEQ_L   144
#define DIM_C   192
#define NHEADS  6
#define HEADD   32
#define NWGRP   64
#define WWINS   15
#define QKVC    576
#define LL      (SEQ_L * SEQ_L)   // 20736

#define QP      36     // q/k smem row stride (frag banks: 4g+tg, conflict-free)
#define VP      40     // v smem row stride (8tg+g, conflict-free)

__device__ float g_qkv[(size_t)B_WIN * SEQ_L * QKVC];            // 318 MB
__device__ float g_ctx[(size_t)B_WIN * SEQ_L * DIM_C];           // 106 MB
__device__ float g_bias[(size_t)NWGRP * NHEADS * LL];            // 31.9 MB

__device__ __forceinline__ uint32_t tf32u(float x) {
    uint32_t u;
    asm("cvt.rna.tf32.f32 %0, %1;" : "=r"(u) : "f"(x));
    return u;
}
__device__ __forceinline__ float tf32f(float x) { return __uint_as_float(tf32u(x)); }

__device__ __forceinline__ void mma_tf32(float c[4], const uint32_t a[4], const uint32_t b[2]) {
    asm volatile(
        "mma.sync.aligned.m16n8k8.row.col.f32.tf32.tf32.f32 "
        "{%0,%1,%2,%3}, {%4,%5,%6,%7}, {%8,%9}, {%0,%1,%2,%3};"
        : "+f"(c[0]), "+f"(c[1]), "+f"(c[2]), "+f"(c[3])
        : "r"(a[0]), "r"(a[1]), "r"(a[2]), "r"(a[3]), "r"(b[0]), "r"(b[1]));
}

// ---------------------------------------------------------------------------
// Bias materialization: g_bias[c][idx] = table[pos[idx]*384 + c], c = nw*6+head
// grid (81, 384) x 256 : 81*256 = 20736 = L*L exactly.
// ---------------------------------------------------------------------------
__global__ __launch_bounds__(256) void bias_mat_kernel(
    const float* __restrict__ table, const int* __restrict__ pos,
    float* __restrict__ out)
{
    const int c   = blockIdx.y;
    const int idx = blockIdx.x * 256 + threadIdx.x;
    out[(size_t)c * LL + idx] = table[(size_t)pos[idx] * (NWGRP * NHEADS) + c];
}

// ---------------------------------------------------------------------------
// tf32 GEMM, cp.async double-buffered:  C[M,N] = A[M,K] @ B[K,N] + bias[N]
// BM=128, BN=64, BK=32, 256 threads, 8 warps 4(M)x2(N), warp tile 32x32.
// ---------------------------------------------------------------------------
__global__ __launch_bounds__(256, 3) void gemm_tf32_kernel(
    const float* __restrict__ A, const float* __restrict__ B,
    const float* __restrict__ bias, float* __restrict__ C,
    int M, int N, int K)
{
    __shared__ float As[2][128][QP];   // [m][k]
    __shared__ float Bs[2][32][72];    // [k][n]

    const int bm   = blockIdx.y * 128;
    const int bn   = blockIdx.x * 64;
    const int tid  = threadIdx.x;
    const int w    = tid >> 5;
    const int lane = tid & 31;
    const int g    = lane >> 2;
    const int tg   = lane & 3;
    const int wm   = (w >> 1) * 32;
    const int wn   = (w & 1) * 32;

    auto load_stage = [&](int buf, int k0) {
        #pragma unroll
        for (int i = 0; i < 4; i++) {
            int idx = tid + i * 256;
            int r = idx >> 3, c = (idx & 7) * 4;
            uint32_t dst = (uint32_t)__cvta_generic_to_shared(&As[buf][r][c]);
            asm volatile("cp.async.ca.shared.global [%0], [%1], 16;"
                         :: "r"(dst), "l"(A + (size_t)(bm + r) * K + k0 + c));
        }
        #pragma unroll
        for (int i = 0; i < 2; i++) {
            int idx = tid + i * 256;
            int r = idx >> 4, c = (idx & 15) * 4;
            uint32_t dst = (uint32_t)__cvta_generic_to_shared(&Bs[buf][r][c]);
            asm volatile("cp.async.ca.shared.global [%0], [%1], 16;"
                         :: "r"(dst), "l"(B + (size_t)(k0 + r) * N + bn + c));
        }
        asm volatile("cp.async.commit_group;");
    };

    float acc[2][4][4] = {};

    load_stage(0, 0);
    const int nk = K >> 5;

    for (int ks = 0; ks < nk; ks++) {
        if (ks + 1 < nk) {
            load_stage((ks + 1) & 1, (ks + 1) << 5);
            asm volatile("cp.async.wait_group 1;");
        } else {
            asm volatile("cp.async.wait_group 0;");
        }
        __syncthreads();

        const int buf = ks & 1;
        #pragma unroll
        for (int kk = 0; kk < 4; kk++) {
            const int k = kk * 8;
            uint32_t af[2][4], bf[4][2];
            #pragma unroll
            for (int mt = 0; mt < 2; mt++) {
                int r0 = wm + mt * 16 + g;
                af[mt][0] = tf32u(As[buf][r0][k + tg]);
                af[mt][1] = tf32u(As[buf][r0 + 8][k + tg]);
                af[mt][2] = tf32u(As[buf][r0][k + tg + 4]);
                af[mt][3] = tf32u(As[buf][r0 + 8][k + tg + 4]);
            }
            #pragma unroll
            for (int nt = 0; nt < 4; nt++) {
                int cn = wn + nt * 8 + g;
                bf[nt][0] = tf32u(Bs[buf][k + tg][cn]);
                bf[nt][1] = tf32u(Bs[buf][k + tg + 4][cn]);
            }
            #pragma unroll
            for (int mt = 0; mt < 2; mt++)
                #pragma unroll
                for (int nt = 0; nt < 4; nt++)
                    mma_tf32(acc[mt][nt], af[mt], bf[nt]);
        }
        __syncthreads();
    }

    #pragma unroll
    for (int mt = 0; mt < 2; mt++) {
        #pragma unroll
        for (int nt = 0; nt < 4; nt++) {
            int r0  = bm + wm + mt * 16 + g;
            int col = bn + wn + nt * 8 + 2 * tg;
            float b0 = bias[col], b1 = bias[col + 1];
            float2 lo = make_float2(acc[mt][nt][0] + b0, acc[mt][nt][1] + b1);
            float2 hi = make_float2(acc[mt][nt][2] + b0, acc[mt][nt][3] + b1);
            *(float2*)&C[(size_t)r0 * N + col]       = lo;
            *(float2*)&C[(size_t)(r0 + 8) * N + col] = hi;
        }
    }
}

// ---------------------------------------------------------------------------
// Fused attention, fully register-resident scores.
// One block per (head, window), 288 threads / 9 warps; warp w owns rows
// [16w,16w+16). smem: q/k/v only (64.5 KB). Softmax + relayout in registers.
// ---------------------------------------------------------------------------
__global__ __launch_bounds__(288, 2) void attn_tf32_kernel(
    const float* __restrict__ qkv,
    const float* __restrict__ mask,
    const float* __restrict__ bias_mat,
    float*       __restrict__ ctx)
{
    const int head = blockIdx.x;
    const int bwin = blockIdx.y;
    const int nw   = (bwin / WWINS) % NWGRP;

    extern __shared__ float sm[];
    float* qS = sm;                       // 144*36
    float* kS = qS + SEQ_L * QP;          // 144*36
    float* vS = kS + SEQ_L * QP;          // 144*40

    const int tid = threadIdx.x;
    const float scale = 0.17677669529663687f;

    // --- load q,k,v (float4 global, tf32-round; q pre-scaled) ---
    {
        const size_t base = (size_t)bwin * SEQ_L * QKVC + head * HEADD;
        for (int idx = tid; idx < SEQ_L * 8; idx += 288) {
            int l = idx >> 3, d = (idx & 7) * 4;
            size_t rb = base + (size_t)l * QKVC + d;
            float4 q4 = *(const float4*)&qkv[rb];
            float4 k4 = *(const float4*)&qkv[rb + DIM_C];
            float4 v4 = *(const float4*)&qkv[rb + 2 * DIM_C];
            *(float4*)&qS[l * QP + d] = make_float4(tf32f(q4.x * scale), tf32f(q4.y * scale),
                                                    tf32f(q4.z * scale), tf32f(q4.w * scale));
            *(float4*)&kS[l * QP + d] = make_float4(tf32f(k4.x), tf32f(k4.y), tf32f(k4.z), tf32f(k4.w));
            *(float4*)&vS[l * VP + d] = make_float4(tf32f(v4.x), tf32f(v4.y), tf32f(v4.z), tf32f(v4.w));
        }
    }
    __syncthreads();

    const int w    = tid >> 5;
    const int lane = tid & 31;
    const int g    = lane >> 2;
    const int tg   = lane & 3;
    const int r0   = 16 * w + g;

    // --- S = q @ k^T : accS[18][4] covers rows {r0, r0+8} x cols {8nt+2tg, +1}
    float accS[18][4] = {};
    #pragma unroll
    for (int kk = 0; kk < 4; kk++) {
        const int k = kk * 8;
        uint32_t af[4];
        af[0] = __float_as_uint(qS[r0 * QP + k + tg]);
        af[1] = __float_as_uint(qS[(r0 + 8) * QP + k + tg]);
        af[2] = __float_as_uint(qS[r0 * QP + k + tg + 4]);
        af[3] = __float_as_uint(qS[(r0 + 8) * QP + k + tg + 4]);
        #pragma unroll
        for (int nt = 0; nt < 18; nt++) {
            int cn = nt * 8 + g;
            uint32_t bf[2];
            bf[0] = __float_as_uint(kS[cn * QP + k + tg]);
            bf[1] = __float_as_uint(kS[cn * QP + k + tg + 4]);
            mma_tf32(accS[nt], af, bf);
        }
    }

    // --- epilogue in regs: + materialized bias + mask; track row maxima ---
    const float* mrow = mask + (size_t)bwin * LL;
    const float* brow = bias_mat + (size_t)(nw * NHEADS + head) * LL;
    float mx0 = -1e30f, mx1 = -1e30f;
    #pragma unroll
    for (int nt = 0; nt < 18; nt++) {
        int col = nt * 8 + 2 * tg;
        int i0 = r0 * SEQ_L + col;
        int i1 = (r0 + 8) * SEQ_L + col;
        float2 m0 = *(const float2*)(mrow + i0);
        float2 b0 = *(const float2*)(brow + i0);
        float2 m1 = *(const float2*)(mrow + i1);
        float2 b1 = *(const float2*)(brow + i1);
        accS[nt][0] += m0.x + b0.x;
        accS[nt][1] += m0.y + b0.y;
        accS[nt][2] += m1.x + b1.x;
        accS[nt][3] += m1.y + b1.y;
        mx0 = fmaxf(mx0, fmaxf(accS[nt][0], accS[nt][1]));
        mx1 = fmaxf(mx1, fmaxf(accS[nt][2], accS[nt][3]));
    }
    // row r0 / r0+8 live in the 4-lane group (same g): quad reduction
    #pragma unroll
    for (int o = 1; o < 4; o <<= 1) {
        mx0 = fmaxf(mx0, __shfl_xor_sync(0xffffffffu, mx0, o));
        mx1 = fmaxf(mx1, __shfl_xor_sync(0xffffffffu, mx1, o));
    }
    float s0 = 0.f, s1 = 0.f;
    #pragma unroll
    for (int nt = 0; nt < 18; nt++) {
        float e0 = __expf(accS[nt][0] - mx0);
        float e1 = __expf(accS[nt][1] - mx0);
        float e2 = __expf(accS[nt][2] - mx1);
        float e3 = __expf(accS[nt][3] - mx1);
        accS[nt][0] = e0; accS[nt][1] = e1; accS[nt][2] = e2; accS[nt][3] = e3;
        s0 += e0 + e1; s1 += e2 + e3;
    }
    #pragma unroll
    for (int o = 1; o < 4; o <<= 1) {
        s0 += __shfl_xor_sync(0xffffffffu, s0, o);
        s1 += __shfl_xor_sync(0xffffffffu, s1, o);
    }
    const float inv0 = 1.f / s0, inv1 = 1.f / s1;
    #pragma unroll
    for (int nt = 0; nt < 18; nt++) {
        accS[nt][0] = tf32f(accS[nt][0] * inv0);
        accS[nt][1] = tf32f(accS[nt][1] * inv0);
        accS[nt][2] = tf32f(accS[nt][2] * inv1);
        accS[nt][3] = tf32f(accS[nt][3] * inv1);
    }

    // --- P @ V: shuffle-relayout C-frag -> A-frag, then mma with vS ---
    float acco[4][4] = {};
    const int src_lo = (g << 2) + (tg >> 1);
    const int src_hi = src_lo + 2;
    const bool sel   = tg & 1;
    #pragma unroll
    for (int kt = 0; kt < 18; kt++) {
        float v0 = __shfl_sync(0xffffffffu, accS[kt][0], src_lo);
        float v1 = __shfl_sync(0xffffffffu, accS[kt][1], src_lo);
        float v2 = __shfl_sync(0xffffffffu, accS[kt][2], src_lo);
        float v3 = __shfl_sync(0xffffffffu, accS[kt][3], src_lo);
        float v4 = __shfl_sync(0xffffffffu, accS[kt][0], src_hi);
        float v5 = __shfl_sync(0xffffffffu, accS[kt][1], src_hi);
        float v6 = __shfl_sync(0xffffffffu, accS[kt][2], src_hi);
        float v7 = __shfl_sync(0xffffffffu, accS[kt][3], src_hi);
        uint32_t a[4];
        a[0] = __float_as_uint(sel ? v1 : v0);
        a[1] = __float_as_uint(sel ? v3 : v2);
        a[2] = __float_as_uint(sel ? v5 : v4);
        a[3] = __float_as_uint(sel ? v7 : v6);
        const int kr = kt * 8;
        #pragma unroll
        for (int nt = 0; nt < 4; nt++) {
            uint32_t bf[2];
            bf[0] = __float_as_uint(vS[(kr + tg) * VP + nt * 8 + g]);
            bf[1] = __float_as_uint(vS[(kr + tg + 4) * VP + nt * 8 + g]);
            mma_tf32(acco[nt], a, bf);
        }
    }

    {
        const size_t obase = (size_t)bwin * SEQ_L * DIM_C + head * HEADD;
        #pragma unroll
        for (int nt = 0; nt < 4; nt++) {
            int col = nt * 8 + 2 * tg;
            *(float2*)&ctx[obase + (size_t)r0 * DIM_C + col] =
                make_float2(acco[nt][0], acco[nt][1]);
            *(float2*)&ctx[obase + (size_t)(r0 + 8) * DIM_C + col] =
                make_float2(acco[nt][2], acco[nt][3]);
        }
    }
}

// ---------------------------------------------------------------------------
extern "C" void kernel_launch(void* const* d_in, const int* in_sizes, int n_in,
                              void* d_out, int out_size)
{
    (void)in_sizes; (void)n_in; (void)out_size;
    const float* x          = (const float*)d_in[0];
    const float* mask       = (const float*)d_in[1];
    const float* W1         = (const float*)d_in[2];
    const float* b1         = (const float*)d_in[3];
    const float* W2         = (const float*)d_in[4];
    const float* b2         = (const float*)d_in[5];
    const float* bias_table = (const float*)d_in[6];
    const int*   pos        = (const int*)d_in[7];
    float*       out        = (float*)d_out;

    float* qkv;  cudaGetSymbolAddress((void**)&qkv, g_qkv);
    float* ctx;  cudaGetSymbolAddress((void**)&ctx, g_ctx);
    float* bmat; cudaGetSymbolAddress((void**)&bmat, g_bias);

    const int M = B_WIN * SEQ_L;  // 138240

    // 0) materialize earth bias: (nw*H, L*L)
    bias_mat_kernel<<<dim3(LL / 256, NWGRP * NHEADS), 256>>>(bias_table, pos, bmat);

    // 1) QKV projection
    gemm_tf32_kernel<<<dim3(QKVC / 64, M / 128), 256>>>(x, W1, b1, qkv, M, QKVC, DIM_C);

    // 2) fused attention (register-resident scores)
    const int smem_bytes = (2 * SEQ_L * QP + SEQ_L * VP) * (int)sizeof(float); // 64512
    cudaFuncSetAttribute(attn_tf32_kernel, cudaFuncAttributeMaxDynamicSharedMemorySize, smem_bytes);
    attn_tf32_kernel<<<dim3(NHEADS, B_WIN), 288, smem_bytes>>>(qkv, mask, bmat, ctx);

    // 3) output projection
    gemm_tf32_kernel<<<dim3(DIM_C / 64, M / 128), 256>>>(ctx, W2, b2, out, M, DIM_C, DIM_C);
}